// round 10
// baseline (speedup 1.0000x reference)
#include <cuda_runtime.h>
#include <math.h>

#define Cn 4096
#define Vn 32000
#define Hn 256
#define Dn 128
#define Nb 16
#define Tt 256

// ---------------- device scratch (static) ----------------
__device__ float g_Xn[Vn * Hn];        // normalized-row staging (max V rows)
__device__ float g_t1[Cn * Hn];
__device__ float g_f1[Cn * Hn];
__device__ float g_t2[Cn * Hn];
__device__ float g_ft[Cn * Hn];
__device__ float g_Eyn[Cn * Dn];       // features of next_state_emb
__device__ float g_Exn[Cn * Dn];       // features of state_emb  (-> row-normalized ExnN)
__device__ float g_Ext[Cn * Dn];       // features of terminal-MLP out (-> ExtN)
__device__ float g_Ele[Vn * Dn];       // features of terminal_emb
__device__ float g_B[(Tt + 1) * Nb * Dn]; // unnormalized G state per step
__device__ float g_Z[(Tt + 1) * Nb];      // per-step normalizers
__device__ float g_Sn[Dn];
__device__ float g_Se[Dn];
__device__ float g_Exs[Dn];

// ---------------- zero ----------------
__global__ __launch_bounds__(256) void kzero() {
    size_t i = (size_t)blockIdx.x * blockDim.x + threadIdx.x;
    size_t st = (size_t)gridDim.x * blockDim.x;
    for (size_t j = i; j < (size_t)(Tt + 1) * Nb * Dn; j += st) g_B[j] = 0.f;
    for (size_t j = i; j < (Tt + 1) * Nb; j += st) g_Z[j] = 0.f;
    if (i < Dn) { g_Sn[i] = 0.f; g_Se[i] = 0.f; }
}

// ------------- generic tiled GEMM: Out = epi(A[M,K]@W[K,N]) -------------
// mode 0: plain; 1: relu(+bias); 2: relu(+bias)+R; 3: exp(x-0.5)
__global__ __launch_bounds__(256) void kgemm(const float* __restrict__ A,
                                             const float* __restrict__ W,
                                             const float* __restrict__ bias,
                                             const float* __restrict__ R,
                                             float* __restrict__ Out,
                                             int M, int N, int K, int mode) {
    __shared__ float As[16][68];
    __shared__ float Ws[16][68];
    int tid = threadIdx.x;
    int m0 = blockIdx.x * 64, n0 = blockIdx.y * 64;
    int ar = tid >> 2, ak = (tid & 3) * 4;
    int wk = tid >> 4, wn = (tid & 15) * 4;
    int ty = tid >> 4, tx = tid & 15;
    float acc[4][4] = {};
    for (int kt = 0; kt < K; kt += 16) {
        float4 av = *(const float4*)(A + (size_t)(m0 + ar) * K + kt + ak);
        As[ak + 0][ar] = av.x; As[ak + 1][ar] = av.y;
        As[ak + 2][ar] = av.z; As[ak + 3][ar] = av.w;
        *(float4*)&Ws[wk][wn] = *(const float4*)(W + (size_t)(kt + wk) * N + n0 + wn);
        __syncthreads();
#pragma unroll
        for (int k = 0; k < 16; k++) {
            float a[4], b[4];
            *(float4*)a = *(const float4*)&As[k][ty * 4];
            *(float4*)b = *(const float4*)&Ws[k][tx * 4];
#pragma unroll
            for (int i = 0; i < 4; i++)
#pragma unroll
                for (int j = 0; j < 4; j++) acc[i][j] += a[i] * b[j];
        }
        __syncthreads();
    }
#pragma unroll
    for (int i = 0; i < 4; i++) {
        int m = m0 + ty * 4 + i;
#pragma unroll
        for (int j = 0; j < 4; j++) {
            int n = n0 + tx * 4 + j;
            float v = acc[i][j];
            if (mode == 1 || mode == 2) v = fmaxf(v + bias[n], 0.f);
            if (mode == 2) v += R[(size_t)m * N + n];
            if (mode == 3) v = expf(v - 0.5f);
            Out[(size_t)m * N + n] = v;
        }
    }
}

// ------------- row l2-normalize: Xn[r,:] = X[r,:]/|X[r,:]| -------------
__global__ __launch_bounds__(256) void krownorm(const float* __restrict__ X,
                                                float* __restrict__ Xn) {
    int r = blockIdx.x, tid = threadIdx.x;
    __shared__ float red[8];
    float v = X[(size_t)r * Hn + tid];
    float ss = v * v;
#pragma unroll
    for (int o = 16; o; o >>= 1) ss += __shfl_xor_sync(~0u, ss, o);
    if ((tid & 31) == 0) red[tid >> 5] = ss;
    __syncthreads();
    float tot = 0.f;
#pragma unroll
    for (int i = 0; i < 8; i++) tot += red[i];
    Xn[(size_t)r * Hn + tid] = v * rsqrtf(tot);
}

// ------------- column sums (feature space) -------------
__global__ __launch_bounds__(128) void kcolsum(const float* __restrict__ E, int rows,
                                               float* __restrict__ S) {
    int d = threadIdx.x;
    float acc = 0.f;
    for (int r = blockIdx.x; r < rows; r += gridDim.x) acc += E[(size_t)r * Dn + d];
    atomicAdd(&S[d], acc);
}

// ------------- row normalize: E[r,:] /= (E[r,:]·S) -------------
__global__ __launch_bounds__(128) void krowdiv(float* __restrict__ E,
                                               const float* __restrict__ S) {
    int r = blockIdx.x, tid = threadIdx.x;
    __shared__ float red[4];
    float v = E[(size_t)r * Dn + tid];
    float p = v * S[tid];
#pragma unroll
    for (int o = 16; o; o >>= 1) p += __shfl_xor_sync(~0u, p, o);
    if ((tid & 31) == 0) red[tid >> 5] = p;
    __syncthreads();
    float u = red[0] + red[1] + red[2] + red[3];
    E[(size_t)r * Dn + tid] = v / u;
}

// ------------- start MLP + features of the single start vector -------------
__global__ __launch_bounds__(256) void kstartmlp(
    const float* se, const float* w0, const float* b0,
    const float* w1, const float* b1, const float* w2, const float* b2,
    const float* w3, const float* b3, const float* w4, const float* b4,
    const float* proj) {
    __shared__ float xs[256], Ab[256], Bb[256], Cb[256];
    __shared__ float red[8], sinv;
    int tid = threadIdx.x;
    xs[tid] = se[tid];
    __syncthreads();
    float acc = 0.f;
    for (int i = 0; i < 256; i++) acc += xs[i] * w0[i * 256 + tid];
    Ab[tid] = acc + b0[tid];
    __syncthreads();
    acc = 0.f;
    for (int i = 0; i < 256; i++) acc += Ab[i] * w1[i * 256 + tid];
    Bb[tid] = fmaxf(acc + b1[tid], 0.f);
    __syncthreads();
    acc = 0.f;
    for (int i = 0; i < 256; i++) acc += Bb[i] * w2[i * 256 + tid];
    Cb[tid] = fmaxf(acc + b2[tid], 0.f) + Ab[tid];
    __syncthreads();
    acc = 0.f;
    for (int i = 0; i < 256; i++) acc += Cb[i] * w3[i * 256 + tid];
    __syncthreads();
    Bb[tid] = fmaxf(acc + b3[tid], 0.f);
    __syncthreads();
    acc = 0.f;
    for (int i = 0; i < 256; i++) acc += Bb[i] * w4[i * 256 + tid];
    Ab[tid] = fmaxf(acc + b4[tid], 0.f) + Cb[tid];
    __syncthreads();
    float ss = Ab[tid] * Ab[tid];
#pragma unroll
    for (int o = 16; o; o >>= 1) ss += __shfl_xor_sync(~0u, ss, o);
    if ((tid & 31) == 0) red[tid >> 5] = ss;
    __syncthreads();
    if (tid == 0) {
        float t = 0.f;
        for (int i = 0; i < 8; i++) t += red[i];
        sinv = rsqrtf(t);
    }
    __syncthreads();
    if (tid < 128) {
        float a2 = 0.f;
        for (int i = 0; i < 256; i++) a2 += Ab[i] * proj[i * 128 + tid];
        g_Exs[tid] = expf(a2 * sinv - 0.5f);
    }
}

// ------------- init recursion state: G slot0 = Exs, Z slot0 = Exs·Sn -------------
__global__ __launch_bounds__(128) void kinit() {
    int tid = threadIdx.x;
    __shared__ float red[4];
    float ex = g_Exs[tid];
    for (int n = 0; n < Nb; n++) g_B[n * Dn + tid] = ex;
    float p = ex * g_Sn[tid];
#pragma unroll
    for (int o = 16; o; o >>= 1) p += __shfl_xor_sync(~0u, p, o);
    if ((tid & 31) == 0) red[tid >> 5] = p;
    __syncthreads();
    float z = red[0] + red[1] + red[2] + red[3];
    if (tid < Nb) g_Z[tid] = z;
}

// ------------- one HMM step -------------
// block: 256 thr, 32 states (8 lanes each, d = j*8 + lane). grid: 128.
__global__ __launch_bounds__(256) void kstep(const int* __restrict__ text, int t) {
    __shared__ float Egs[Nb][Dn];
    __shared__ float Gs[Nb][Dn];
    __shared__ float As[Nb][32];
    __shared__ int stok[Nb];
    __shared__ float sinv[Nb];
    int tid = threadIdx.x;
    const float* Gprev = g_B + (size_t)t * (Nb * Dn);
    float* Gnext = g_B + (size_t)(t + 1) * (Nb * Dn);
    if (tid < Nb) {
        stok[tid] = text[tid * Tt + t];
        sinv[tid] = 1.0f / g_Z[t * Nb + tid];
    }
    __syncthreads();
    for (int i = tid; i < Nb * Dn; i += 256) {
        int n = i >> 7, d = i & 127;
        Egs[n][d] = g_Ele[(size_t)stok[n] * Dn + d];
        Gs[n][d] = Gprev[i] * sinv[n];
    }
    __syncthreads();
    int cl = tid >> 3, q = tid & 7;
    int c = blockIdx.x * 32 + cl;
    const float* ap = g_Ext + (size_t)c * Dn;  // ExtN (row-normalized)
    const float* bp = g_Eyn + (size_t)c * Dn;
    float a[16], b[16];
#pragma unroll
    for (int j = 0; j < 16; j++) { a[j] = ap[j * 8 + q]; b[j] = bp[j * 8 + q]; }
#pragma unroll
    for (int n = 0; n < Nb; n++) {
        float eo = 0.f, mo = 0.f;
#pragma unroll
        for (int j = 0; j < 16; j++) {
            eo += a[j] * Egs[n][j * 8 + q];
            mo += b[j] * Gs[n][j * 8 + q];
        }
#pragma unroll
        for (int o = 4; o; o >>= 1) {
            eo += __shfl_xor_sync(~0u, eo, o);
            mo += __shfl_xor_sync(~0u, mo, o);
        }
        if (q == 0) As[n][cl] = eo * mo;
    }
    __syncthreads();
    if (tid < Nb) {
        float z = 0.f;
#pragma unroll
        for (int k = 0; k < 32; k++) z += As[tid][k];
        atomicAdd(&g_Z[(t + 1) * Nb + tid], z);
    }
#pragma unroll
    for (int k = 0; k < 8; k++) {
        int o = k * 256 + tid;
        int n = o >> 7, d = o & 127;
        float acc = 0.f;
        const float* xb = g_Exn + (size_t)(blockIdx.x * 32) * Dn + d;  // ExnN
#pragma unroll 8
        for (int k2 = 0; k2 < 32; k2++) acc += As[n][k2] * xb[k2 * Dn];
        atomicAdd(&Gnext[o], acc);
    }
}

// ------------- evidence = sum of log Z over all (t,n) -------------
__global__ __launch_bounds__(256) void kfinal(float* __restrict__ out) {
    int tid = threadIdx.x;
    __shared__ float red[8];
    float s = 0.f;
    for (int i = tid; i < Tt * Nb; i += 256) s += logf(g_Z[Nb + i]);
#pragma unroll
    for (int o = 16; o; o >>= 1) s += __shfl_xor_sync(~0u, s, o);
    if ((tid & 31) == 0) red[tid >> 5] = s;
    __syncthreads();
    if (tid == 0) {
        float t = 0.f;
        for (int i = 0; i < 8; i++) t += red[i];
        out[0] = t;
    }
}

extern "C" void kernel_launch(void* const* d_in, const int* in_sizes, int n_in,
                              void* d_out, int out_size) {
    (void)n_in; (void)out_size;
    const float *se, *sw0, *sb0, *sw1, *sb1, *sw2, *sb2, *sw3, *sb3, *sw4, *sb4;
    const float *state_emb, *next_state_emb, *pre_emb;
    const float *tw1, *tb1, *tw2, *tb2, *tw3, *tb3, *tw4, *tb4, *term_emb, *proj;
    const int* text;
    if (in_sizes[0] == Hn) {
        // reference-signature order
        se  = (const float*)d_in[0];
        sw0 = (const float*)d_in[1];  sb0 = (const float*)d_in[2];
        sw1 = (const float*)d_in[3];  sb1 = (const float*)d_in[4];
        sw2 = (const float*)d_in[5];  sb2 = (const float*)d_in[6];
        sw3 = (const float*)d_in[7];  sb3 = (const float*)d_in[8];
        sw4 = (const float*)d_in[9];  sb4 = (const float*)d_in[10];
        state_emb = (const float*)d_in[11];
        next_state_emb = (const float*)d_in[12];
        pre_emb = (const float*)d_in[13];
        tw1 = (const float*)d_in[14]; tb1 = (const float*)d_in[15];
        tw2 = (const float*)d_in[16]; tb2 = (const float*)d_in[17];
        tw3 = (const float*)d_in[18]; tb3 = (const float*)d_in[19];
        tw4 = (const float*)d_in[20]; tb4 = (const float*)d_in[21];
        term_emb = (const float*)d_in[22];
        proj = (const float*)d_in[23];
        text = (const int*)d_in[24];
    } else {
        // setup_inputs dict order: text, mask, start_emb, sw0,sb0..sw4,sb4,
        // tw1,tb1..tw4,tb4, state_emb, next_state_emb, preterminal_emb,
        // terminal_emb, proj
        text = (const int*)d_in[0];
        se  = (const float*)d_in[2];
        sw0 = (const float*)d_in[3];  sb0 = (const float*)d_in[4];
        sw1 = (const float*)d_in[5];  sb1 = (const float*)d_in[6];
        sw2 = (const float*)d_in[7];  sb2 = (const float*)d_in[8];
        sw3 = (const float*)d_in[9];  sb3 = (const float*)d_in[10];
        sw4 = (const float*)d_in[11]; sb4 = (const float*)d_in[12];
        tw1 = (const float*)d_in[13]; tb1 = (const float*)d_in[14];
        tw2 = (const float*)d_in[15]; tb2 = (const float*)d_in[16];
        tw3 = (const float*)d_in[17]; tb3 = (const float*)d_in[18];
        tw4 = (const float*)d_in[19]; tb4 = (const float*)d_in[20];
        state_emb = (const float*)d_in[21];
        next_state_emb = (const float*)d_in[22];
        pre_emb = (const float*)d_in[23];
        term_emb = (const float*)d_in[24];
        proj = (const float*)d_in[25];
    }

    float *pXn, *pT1, *pF1, *pT2, *pFt, *pEyn, *pExn, *pExt, *pEle, *pSn, *pSe;
    cudaGetSymbolAddress((void**)&pXn, g_Xn);
    cudaGetSymbolAddress((void**)&pT1, g_t1);
    cudaGetSymbolAddress((void**)&pF1, g_f1);
    cudaGetSymbolAddress((void**)&pT2, g_t2);
    cudaGetSymbolAddress((void**)&pFt, g_ft);
    cudaGetSymbolAddress((void**)&pEyn, g_Eyn);
    cudaGetSymbolAddress((void**)&pExn, g_Exn);
    cudaGetSymbolAddress((void**)&pExt, g_Ext);
    cudaGetSymbolAddress((void**)&pEle, g_Ele);
    cudaGetSymbolAddress((void**)&pSn, g_Sn);
    cudaGetSymbolAddress((void**)&pSe, g_Se);

    kzero<<<256, 256>>>();

    // terminal MLP: two ResLayers on preterminal_emb
    kgemm<<<dim3(Cn / 64, 4), 256>>>(pre_emb, tw1, tb1, nullptr, pT1, Cn, Hn, Hn, 1);
    kgemm<<<dim3(Cn / 64, 4), 256>>>(pT1, tw2, tb2, pre_emb, pF1, Cn, Hn, Hn, 2);
    kgemm<<<dim3(Cn / 64, 4), 256>>>(pF1, tw3, tb3, nullptr, pT2, Cn, Hn, Hn, 1);
    kgemm<<<dim3(Cn / 64, 4), 256>>>(pT2, tw4, tb4, pF1, pFt, Cn, Hn, Hn, 2);

    // features
    krownorm<<<Cn, 256>>>(next_state_emb, pXn);
    kgemm<<<dim3(Cn / 64, 2), 256>>>(pXn, proj, nullptr, nullptr, pEyn, Cn, Dn, Hn, 3);
    kcolsum<<<256, 128>>>(pEyn, Cn, pSn);

    krownorm<<<Cn, 256>>>(state_emb, pXn);
    kgemm<<<dim3(Cn / 64, 2), 256>>>(pXn, proj, nullptr, nullptr, pExn, Cn, Dn, Hn, 3);
    krowdiv<<<Cn, 128>>>(pExn, pSn);   // -> ExnN

    krownorm<<<Cn, 256>>>(pFt, pXn);
    kgemm<<<dim3(Cn / 64, 2), 256>>>(pXn, proj, nullptr, nullptr, pExt, Cn, Dn, Hn, 3);

    krownorm<<<Vn, 256>>>(term_emb, pXn);
    kgemm<<<dim3(Vn / 64, 2), 256>>>(pXn, proj, nullptr, nullptr, pEle, Vn, Dn, Hn, 3);
    kcolsum<<<256, 128>>>(pEle, Vn, pSe);
    krowdiv<<<Cn, 128>>>(pExt, pSe);   // -> ExtN

    kstartmlp<<<1, 256>>>(se, sw0, sb0, sw1, sb1, sw2, sb2, sw3, sb3, sw4, sb4, proj);
    kinit<<<1, 128>>>();

    for (int t = 0; t < Tt; t++) kstep<<<128, 256>>>(text, t);

    kfinal<<<1, 256>>>((float*)d_out);
}

// round 11
// speedup vs baseline: 1.4463x; 1.4463x over previous
#include <cuda_runtime.h>
#include <math.h>

#define Cn 4096
#define Vn 32000
#define Hn 256
#define Dn 128
#define Nb 16
#define Tt 256
#define NBLK 128

// ---------------- device scratch (static) ----------------
__device__ float g_Xn[Vn * Hn];        // normalized-row staging (max V rows)
__device__ float g_t1[Cn * Hn];
__device__ float g_f1[Cn * Hn];
__device__ float g_t2[Cn * Hn];
__device__ float g_ft[Cn * Hn];
__device__ float g_Eyn[Cn * Dn];       // features of next_state_emb
__device__ float g_Exn[Cn * Dn];       // features of state_emb (row-normalized: ExnN·Sn = 1)
__device__ float g_Ext[Cn * Dn];       // features of terminal-MLP out (row-normalized by Se)
__device__ float g_Ele[Vn * Dn];       // features of terminal_emb
__device__ float g_Sn[Dn];
__device__ float g_Se[Dn];
__device__ float g_Exs[Dn];
__device__ float g_buf[3][Nb][Dn];     // rotating G state buffers
__device__ unsigned g_bar;
__device__ volatile unsigned g_gen;

// ---------------- zero / reset ----------------
__global__ __launch_bounds__(128) void kzero() {
    int i = threadIdx.x;
    if (i < Dn) { g_Sn[i] = 0.f; g_Se[i] = 0.f; }
    if (i == 0) { g_bar = 0u; g_gen = 0u; }
}

// ------------- generic tiled GEMM: Out = epi(A[M,K]@W[K,N]) -------------
// mode 1: relu(+bias); 2: relu(+bias)+R; 3: exp(x-0.5)
__global__ __launch_bounds__(256) void kgemm(const float* __restrict__ A,
                                             const float* __restrict__ W,
                                             const float* __restrict__ bias,
                                             const float* __restrict__ R,
                                             float* __restrict__ Out,
                                             int M, int N, int K, int mode) {
    __shared__ float As[16][68];
    __shared__ float Ws[16][68];
    int tid = threadIdx.x;
    int m0 = blockIdx.x * 64, n0 = blockIdx.y * 64;
    int ar = tid >> 2, ak = (tid & 3) * 4;
    int wk = tid >> 4, wn = (tid & 15) * 4;
    int ty = tid >> 4, tx = tid & 15;
    float acc[4][4] = {};
    for (int kt = 0; kt < K; kt += 16) {
        float4 av = *(const float4*)(A + (size_t)(m0 + ar) * K + kt + ak);
        As[ak + 0][ar] = av.x; As[ak + 1][ar] = av.y;
        As[ak + 2][ar] = av.z; As[ak + 3][ar] = av.w;
        *(float4*)&Ws[wk][wn] = *(const float4*)(W + (size_t)(kt + wk) * N + n0 + wn);
        __syncthreads();
#pragma unroll
        for (int k = 0; k < 16; k++) {
            float a[4], b[4];
            *(float4*)a = *(const float4*)&As[k][ty * 4];
            *(float4*)b = *(const float4*)&Ws[k][tx * 4];
#pragma unroll
            for (int i = 0; i < 4; i++)
#pragma unroll
                for (int j = 0; j < 4; j++) acc[i][j] += a[i] * b[j];
        }
        __syncthreads();
    }
#pragma unroll
    for (int i = 0; i < 4; i++) {
        int m = m0 + ty * 4 + i;
#pragma unroll
        for (int j = 0; j < 4; j++) {
            int n = n0 + tx * 4 + j;
            float v = acc[i][j];
            if (mode == 1 || mode == 2) v = fmaxf(v + bias[n], 0.f);
            if (mode == 2) v += R[(size_t)m * N + n];
            if (mode == 3) v = expf(v - 0.5f);
            Out[(size_t)m * N + n] = v;
        }
    }
}

// ------------- row l2-normalize -------------
__global__ __launch_bounds__(256) void krownorm(const float* __restrict__ X,
                                                float* __restrict__ Xn) {
    int r = blockIdx.x, tid = threadIdx.x;
    __shared__ float red[8];
    float v = X[(size_t)r * Hn + tid];
    float ss = v * v;
#pragma unroll
    for (int o = 16; o; o >>= 1) ss += __shfl_xor_sync(~0u, ss, o);
    if ((tid & 31) == 0) red[tid >> 5] = ss;
    __syncthreads();
    float tot = 0.f;
#pragma unroll
    for (int i = 0; i < 8; i++) tot += red[i];
    Xn[(size_t)r * Hn + tid] = v * rsqrtf(tot);
}

// ------------- column sums -------------
__global__ __launch_bounds__(128) void kcolsum(const float* __restrict__ E, int rows,
                                               float* __restrict__ S) {
    int d = threadIdx.x;
    float acc = 0.f;
    for (int r = blockIdx.x; r < rows; r += gridDim.x) acc += E[(size_t)r * Dn + d];
    atomicAdd(&S[d], acc);
}

// ------------- row normalize: E[r,:] /= (E[r,:]·S) -------------
__global__ __launch_bounds__(128) void krowdiv(float* __restrict__ E,
                                               const float* __restrict__ S) {
    int r = blockIdx.x, tid = threadIdx.x;
    __shared__ float red[4];
    float v = E[(size_t)r * Dn + tid];
    float p = v * S[tid];
#pragma unroll
    for (int o = 16; o; o >>= 1) p += __shfl_xor_sync(~0u, p, o);
    if ((tid & 31) == 0) red[tid >> 5] = p;
    __syncthreads();
    float u = red[0] + red[1] + red[2] + red[3];
    E[(size_t)r * Dn + tid] = v / u;
}

// ------------- start MLP + features of the single start vector -------------
__global__ __launch_bounds__(256) void kstartmlp(
    const float* se, const float* w0, const float* b0,
    const float* w1, const float* b1, const float* w2, const float* b2,
    const float* w3, const float* b3, const float* w4, const float* b4,
    const float* proj) {
    __shared__ float xs[256], Ab[256], Bb[256], Cb[256];
    __shared__ float red[8], sinv;
    int tid = threadIdx.x;
    xs[tid] = se[tid];
    __syncthreads();
    float acc = 0.f;
    for (int i = 0; i < 256; i++) acc += xs[i] * w0[i * 256 + tid];
    Ab[tid] = acc + b0[tid];
    __syncthreads();
    acc = 0.f;
    for (int i = 0; i < 256; i++) acc += Ab[i] * w1[i * 256 + tid];
    Bb[tid] = fmaxf(acc + b1[tid], 0.f);
    __syncthreads();
    acc = 0.f;
    for (int i = 0; i < 256; i++) acc += Bb[i] * w2[i * 256 + tid];
    Cb[tid] = fmaxf(acc + b2[tid], 0.f) + Ab[tid];
    __syncthreads();
    acc = 0.f;
    for (int i = 0; i < 256; i++) acc += Cb[i] * w3[i * 256 + tid];
    __syncthreads();
    Bb[tid] = fmaxf(acc + b3[tid], 0.f);
    __syncthreads();
    acc = 0.f;
    for (int i = 0; i < 256; i++) acc += Bb[i] * w4[i * 256 + tid];
    Ab[tid] = fmaxf(acc + b4[tid], 0.f) + Cb[tid];
    __syncthreads();
    float ss = Ab[tid] * Ab[tid];
#pragma unroll
    for (int o = 16; o; o >>= 1) ss += __shfl_xor_sync(~0u, ss, o);
    if ((tid & 31) == 0) red[tid >> 5] = ss;
    __syncthreads();
    if (tid == 0) {
        float t = 0.f;
        for (int i = 0; i < 8; i++) t += red[i];
        sinv = rsqrtf(t);
    }
    __syncthreads();
    if (tid < 128) {
        float a2 = 0.f;
        for (int i = 0; i < 256; i++) a2 += Ab[i] * proj[i * 128 + tid];
        g_Exs[tid] = expf(a2 * sinv - 0.5f);
    }
}

// =========== persistent recursion kernel: all 256 HMM steps ===========
// 128 blocks x 256 threads, all co-resident; software grid barrier.
#define GRIDBAR()                                                              \
    do {                                                                       \
        __threadfence();                                                       \
        __syncthreads();                                                       \
        if (tid == 0) {                                                        \
            if (atomicAdd(&g_bar, 1u) == NBLK - 1u) {                          \
                atomicExch(&g_bar, 0u);                                        \
                __threadfence();                                               \
                atomicAdd((unsigned*)&g_gen, 1u);                              \
            } else {                                                           \
                while (g_gen <= gen) __nanosleep(64);                          \
            }                                                                  \
        }                                                                      \
        __syncthreads();                                                       \
        gen++;                                                                 \
    } while (0)

__global__ __launch_bounds__(256, 1) void krec(const int* __restrict__ text,
                                               float* __restrict__ out) {
    __shared__ float Gs[Nb][Dn];
    __shared__ float Egs[Nb][Dn];
    __shared__ float Ash[Nb][32];
    __shared__ float zsh[Nb];
    __shared__ float snS[Dn];
    int tid = threadIdx.x;
    int blk = blockIdx.x;
    int w = tid >> 5, lane = tid & 31;
    int cl = tid >> 3, q = tid & 7;
    int dd = tid & 127, half = tid >> 7;
    unsigned gen = 0;

    // persistent operands: thread owns d-chunks {j*32 + q*4 .. +3} of its state row
    float a[16], b[16], xn[32];
    {
        const float4* ap = (const float4*)(g_Ext + (size_t)(blk * 32 + cl) * Dn + q * 4);
        const float4* bp = (const float4*)(g_Eyn + (size_t)(blk * 32 + cl) * Dn + q * 4);
#pragma unroll
        for (int j = 0; j < 4; j++) {
            *(float4*)&a[j * 4] = ap[j * 8];   // stride 32 floats = 8 float4
            *(float4*)&b[j * 4] = bp[j * 8];
        }
#pragma unroll
        for (int k = 0; k < 32; k++) xn[k] = g_Exn[(size_t)(blk * 32 + k) * Dn + dd];
    }
    if (tid < Dn) snS[tid] = g_Sn[tid];

    // init rotating buffers: buf0 = Exs replicated, buf1 = 0
    if (tid < 16) {
        int ib = blk * 16 + tid;
        __stcg(&((float*)g_buf[0])[ib], g_Exs[ib & 127]);
        __stcg(&((float*)g_buf[1])[ib], 0.f);
    }
    float evAcc = 0.f;
    GRIDBAR();

    float* bufp0 = (float*)g_buf[0];
    float* bufp1 = (float*)g_buf[1];
    float* bufp2 = (float*)g_buf[2];

    for (int t = 0; t < Tt; t++) {
        const float* Gcur = bufp0;
        float* Gnext = bufp1;
        float* Gz = bufp2;

        // token + Ele gather (overlaps the z pass)
        float egv[8];
#pragma unroll
        for (int k = 0; k < 8; k++) {
            int i = k * 256 + tid, n = i >> 7, d = i & 127;
            int tk = __ldg(&text[n * Tt + t]);
            egv[k] = __ldg(&g_Ele[(size_t)tk * Dn + d]);
        }

        // z[n] = G[n,:]·Sn ; ghat = G/z
        float4 ga = __ldcg((const float4*)(Gcur + w * Dn + lane * 4));
        float4 gb = __ldcg((const float4*)(Gcur + (w + 8) * Dn + lane * 4));
        float4 s4 = *(const float4*)&snS[lane * 4];
        float za = ga.x * s4.x + ga.y * s4.y + ga.z * s4.z + ga.w * s4.w;
        float zb = gb.x * s4.x + gb.y * s4.y + gb.z * s4.z + gb.w * s4.w;
#pragma unroll
        for (int o = 16; o; o >>= 1) {
            za += __shfl_xor_sync(~0u, za, o);
            zb += __shfl_xor_sync(~0u, zb, o);
        }
        if (lane == 0) { zsh[w] = za; zsh[w + 8] = zb; }
        __syncthreads();
        float ia = 1.f / zsh[w], ib = 1.f / zsh[w + 8];
        ga.x *= ia; ga.y *= ia; ga.z *= ia; ga.w *= ia;
        gb.x *= ib; gb.y *= ib; gb.z *= ib; gb.w *= ib;
        *(float4*)&Gs[w][lane * 4] = ga;
        *(float4*)&Gs[w + 8][lane * 4] = gb;
#pragma unroll
        for (int k = 0; k < 8; k++) ((float*)Egs)[k * 256 + tid] = egv[k];
        if (blk == 0 && tid < 16 && t > 0) evAcc += logf(zsh[tid]);
        __syncthreads();

        // A[n,c] = (ExtN_c·Ele_n) * (ghat_n·Eyn_c)
#pragma unroll
        for (int n = 0; n < Nb; n++) {
            float eo = 0.f, mo = 0.f;
#pragma unroll
            for (int j = 0; j < 4; j++) {
                float4 e = *(const float4*)&Egs[n][j * 32 + q * 4];
                float4 g = *(const float4*)&Gs[n][j * 32 + q * 4];
                eo += a[j * 4] * e.x + a[j * 4 + 1] * e.y + a[j * 4 + 2] * e.z + a[j * 4 + 3] * e.w;
                mo += b[j * 4] * g.x + b[j * 4 + 1] * g.y + b[j * 4 + 2] * g.z + b[j * 4 + 3] * g.w;
            }
#pragma unroll
            for (int o = 4; o; o >>= 1) {
                eo += __shfl_xor_sync(~0u, eo, o);
                mo += __shfl_xor_sync(~0u, mo, o);
            }
            if (q == 0) Ash[n][cl] = eo * mo;
        }
        __syncthreads();

        // G'[n,d] += A[n, block slice] @ ExnN[block slice, d]
#pragma unroll
        for (int k = 0; k < 8; k++) {
            int n = 2 * k + half;
            float acc = 0.f;
            const float* ar = Ash[n];
#pragma unroll
            for (int c2 = 0; c2 < 32; c2++) acc += ar[c2] * xn[c2];
            atomicAdd(&Gnext[n * Dn + dd], acc);
        }
        // zero the buffer that step t+1 will accumulate into at t+2
        if (tid < 16) __stcg(&Gz[blk * 16 + tid], 0.f);

        GRIDBAR();
        float* tmp = bufp0; bufp0 = bufp1; bufp1 = bufp2; bufp2 = tmp;
    }

    // finalize: block 0 adds log Z[256] and reduces evidence
    if (blk == 0) {
        const float* Gf = bufp0;
        float4 ga = __ldcg((const float4*)(Gf + w * Dn + lane * 4));
        float4 gb = __ldcg((const float4*)(Gf + (w + 8) * Dn + lane * 4));
        float4 s4 = *(const float4*)&snS[lane * 4];
        float za = ga.x * s4.x + ga.y * s4.y + ga.z * s4.z + ga.w * s4.w;
        float zb = gb.x * s4.x + gb.y * s4.y + gb.z * s4.z + gb.w * s4.w;
#pragma unroll
        for (int o = 16; o; o >>= 1) {
            za += __shfl_xor_sync(~0u, za, o);
            zb += __shfl_xor_sync(~0u, zb, o);
        }
        if (lane == 0) { zsh[w] = za; zsh[w + 8] = zb; }
        __syncthreads();
        if (tid < 16) evAcc += logf(zsh[tid]);
        if (w == 0) {
#pragma unroll
            for (int o = 8; o; o >>= 1) evAcc += __shfl_xor_sync(~0u, evAcc, o);
            if (tid == 0) out[0] = evAcc;
        }
    }
}

extern "C" void kernel_launch(void* const* d_in, const int* in_sizes, int n_in,
                              void* d_out, int out_size) {
    (void)n_in; (void)out_size;
    const float *se, *sw0, *sb0, *sw1, *sb1, *sw2, *sb2, *sw3, *sb3, *sw4, *sb4;
    const float *state_emb, *next_state_emb, *pre_emb;
    const float *tw1, *tb1, *tw2, *tb2, *tw3, *tb3, *tw4, *tb4, *term_emb, *proj;
    const int* text;
    if (in_sizes[0] == Hn) {
        se  = (const float*)d_in[0];
        sw0 = (const float*)d_in[1];  sb0 = (const float*)d_in[2];
        sw1 = (const float*)d_in[3];  sb1 = (const float*)d_in[4];
        sw2 = (const float*)d_in[5];  sb2 = (const float*)d_in[6];
        sw3 = (const float*)d_in[7];  sb3 = (const float*)d_in[8];
        sw4 = (const float*)d_in[9];  sb4 = (const float*)d_in[10];
        state_emb = (const float*)d_in[11];
        next_state_emb = (const float*)d_in[12];
        pre_emb = (const float*)d_in[13];
        tw1 = (const float*)d_in[14]; tb1 = (const float*)d_in[15];
        tw2 = (const float*)d_in[16]; tb2 = (const float*)d_in[17];
        tw3 = (const float*)d_in[18]; tb3 = (const float*)d_in[19];
        tw4 = (const float*)d_in[20]; tb4 = (const float*)d_in[21];
        term_emb = (const float*)d_in[22];
        proj = (const float*)d_in[23];
        text = (const int*)d_in[24];
    } else {
        text = (const int*)d_in[0];
        se  = (const float*)d_in[2];
        sw0 = (const float*)d_in[3];  sb0 = (const float*)d_in[4];
        sw1 = (const float*)d_in[5];  sb1 = (const float*)d_in[6];
        sw2 = (const float*)d_in[7];  sb2 = (const float*)d_in[8];
        sw3 = (const float*)d_in[9];  sb3 = (const float*)d_in[10];
        sw4 = (const float*)d_in[11]; sb4 = (const float*)d_in[12];
        tw1 = (const float*)d_in[13]; tb1 = (const float*)d_in[14];
        tw2 = (const float*)d_in[15]; tb2 = (const float*)d_in[16];
        tw3 = (const float*)d_in[17]; tb3 = (const float*)d_in[18];
        tw4 = (const float*)d_in[19]; tb4 = (const float*)d_in[20];
        state_emb = (const float*)d_in[21];
        next_state_emb = (const float*)d_in[22];
        pre_emb = (const float*)d_in[23];
        term_emb = (const float*)d_in[24];
        proj = (const float*)d_in[25];
    }

    float *pXn, *pT1, *pF1, *pT2, *pFt, *pEyn, *pExn, *pExt, *pEle, *pSn, *pSe;
    cudaGetSymbolAddress((void**)&pXn, g_Xn);
    cudaGetSymbolAddress((void**)&pT1, g_t1);
    cudaGetSymbolAddress((void**)&pF1, g_f1);
    cudaGetSymbolAddress((void**)&pT2, g_t2);
    cudaGetSymbolAddress((void**)&pFt, g_ft);
    cudaGetSymbolAddress((void**)&pEyn, g_Eyn);
    cudaGetSymbolAddress((void**)&pExn, g_Exn);
    cudaGetSymbolAddress((void**)&pExt, g_Ext);
    cudaGetSymbolAddress((void**)&pEle, g_Ele);
    cudaGetSymbolAddress((void**)&pSn, g_Sn);
    cudaGetSymbolAddress((void**)&pSe, g_Se);

    kzero<<<1, 128>>>();

    // terminal MLP: two ResLayers on preterminal_emb
    kgemm<<<dim3(Cn / 64, 4), 256>>>(pre_emb, tw1, tb1, nullptr, pT1, Cn, Hn, Hn, 1);
    kgemm<<<dim3(Cn / 64, 4), 256>>>(pT1, tw2, tb2, pre_emb, pF1, Cn, Hn, Hn, 2);
    kgemm<<<dim3(Cn / 64, 4), 256>>>(pF1, tw3, tb3, nullptr, pT2, Cn, Hn, Hn, 1);
    kgemm<<<dim3(Cn / 64, 4), 256>>>(pT2, tw4, tb4, pF1, pFt, Cn, Hn, Hn, 2);

    // features
    krownorm<<<Cn, 256>>>(next_state_emb, pXn);
    kgemm<<<dim3(Cn / 64, 2), 256>>>(pXn, proj, nullptr, nullptr, pEyn, Cn, Dn, Hn, 3);
    kcolsum<<<256, 128>>>(pEyn, Cn, pSn);

    krownorm<<<Cn, 256>>>(state_emb, pXn);
    kgemm<<<dim3(Cn / 64, 2), 256>>>(pXn, proj, nullptr, nullptr, pExn, Cn, Dn, Hn, 3);
    krowdiv<<<Cn, 128>>>(pExn, pSn);   // ExnN: rows sum to 1 against Sn

    krownorm<<<Cn, 256>>>(pFt, pXn);
    kgemm<<<dim3(Cn / 64, 2), 256>>>(pXn, proj, nullptr, nullptr, pExt, Cn, Dn, Hn, 3);

    krownorm<<<Vn, 256>>>(term_emb, pXn);
    kgemm<<<dim3(Vn / 64, 2), 256>>>(pXn, proj, nullptr, nullptr, pEle, Vn, Dn, Hn, 3);
    kcolsum<<<256, 128>>>(pEle, Vn, pSe);
    krowdiv<<<Cn, 128>>>(pExt, pSe);   // ExtN

    kstartmlp<<<1, 256>>>(se, sw0, sb0, sw1, sb1, sw2, sb2, sw3, sb3, sw4, sb4, proj);

    // the whole 256-step recursion in ONE launch
    krec<<<NBLK, 256>>>(text, (float*)d_out);
}